// round 1
// baseline (speedup 1.0000x reference)
#include <cuda_runtime.h>
#include <math.h>

#define SLEN 4096
#define DMODEL 1024
#define NHEAD 16
#define HDIM 64

// scratch (allocation-free rule: __device__ globals)
__device__ float g_q[SLEN * DMODEL];
__device__ float g_k[SLEN * DMODEL];
__device__ float g_v[SLEN * DMODEL];
__device__ float g_attn[SLEN * DMODEL];

// ---------------------------------------------------------------------------
// C[M][N] = A[M][K] @ B[N][K]^T + bias[N]   (torch Linear layout: NT gemm)
// BM=BN=128, BK=8, 256 threads, 8x8 micro-tile per thread.
// ---------------------------------------------------------------------------
__global__ __launch_bounds__(256) void sgemm_nt(
    const float* __restrict__ A, const float* __restrict__ B,
    const float* __restrict__ bias, float* __restrict__ C,
    int M, int N, int K)
{
    __shared__ float As[8][128];
    __shared__ float Bs[8][128];

    const int tid  = threadIdx.x;
    const int brow = blockIdx.y * 128;
    const int bcol = blockIdx.x * 128;

    const int lrow = tid >> 1;          // 0..127
    const int lcol = (tid & 1) * 4;     // 0 or 4
    const int tr   = (tid >> 4) * 8;    // micro-tile row
    const int tc   = (tid & 15) * 8;    // micro-tile col

    float acc[8][8];
#pragma unroll
    for (int i = 0; i < 8; i++)
#pragma unroll
        for (int j = 0; j < 8; j++) acc[i][j] = 0.f;

    const float* Aptr = A + (size_t)(brow + lrow) * K + lcol;
    const float* Bptr = B + (size_t)(bcol + lrow) * K + lcol;

    for (int k0 = 0; k0 < K; k0 += 8) {
        float4 a4 = *(const float4*)(Aptr + k0);
        float4 b4 = *(const float4*)(Bptr + k0);
        As[lcol + 0][lrow] = a4.x; As[lcol + 1][lrow] = a4.y;
        As[lcol + 2][lrow] = a4.z; As[lcol + 3][lrow] = a4.w;
        Bs[lcol + 0][lrow] = b4.x; Bs[lcol + 1][lrow] = b4.y;
        Bs[lcol + 2][lrow] = b4.z; Bs[lcol + 3][lrow] = b4.w;
        __syncthreads();
#pragma unroll
        for (int kk = 0; kk < 8; kk++) {
            float ar[8], br[8];
            float4 t0 = *(const float4*)&As[kk][tr];
            float4 t1 = *(const float4*)&As[kk][tr + 4];
            ar[0]=t0.x; ar[1]=t0.y; ar[2]=t0.z; ar[3]=t0.w;
            ar[4]=t1.x; ar[5]=t1.y; ar[6]=t1.z; ar[7]=t1.w;
            float4 u0 = *(const float4*)&Bs[kk][tc];
            float4 u1 = *(const float4*)&Bs[kk][tc + 4];
            br[0]=u0.x; br[1]=u0.y; br[2]=u0.z; br[3]=u0.w;
            br[4]=u1.x; br[5]=u1.y; br[6]=u1.z; br[7]=u1.w;
#pragma unroll
            for (int i = 0; i < 8; i++)
#pragma unroll
                for (int j = 0; j < 8; j++)
                    acc[i][j] += ar[i] * br[j];
        }
        __syncthreads();
    }

    float bvv[8];
#pragma unroll
    for (int j = 0; j < 8; j++) bvv[j] = bias ? bias[bcol + tc + j] : 0.f;

#pragma unroll
    for (int i = 0; i < 8; i++) {
        float* cp = C + (size_t)(brow + tr + i) * N + bcol + tc;
        float4 r0, r1;
        r0.x = acc[i][0] + bvv[0]; r0.y = acc[i][1] + bvv[1];
        r0.z = acc[i][2] + bvv[2]; r0.w = acc[i][3] + bvv[3];
        r1.x = acc[i][4] + bvv[4]; r1.y = acc[i][5] + bvv[5];
        r1.z = acc[i][6] + bvv[6]; r1.w = acc[i][7] + bvv[7];
        *(float4*)cp       = r0;
        *(float4*)(cp + 4) = r1;
    }
}

// ---------------------------------------------------------------------------
// Causal flash attention with ALiBi key-position bias.
// Q/K/V stored [S][D] with head h at columns h*64..h*64+63.
// Block: (query tile of 64 rows, head). 256 threads.
// BQ=64, BT=32. Thread owns rows tr..tr+3, cols cg+16*j.
// ---------------------------------------------------------------------------
#define BQ 64
#define BT 32

__global__ __launch_bounds__(256) void flash_attn(
    const float* __restrict__ Q, const float* __restrict__ K,
    const float* __restrict__ V, float* __restrict__ O)
{
    const int h  = blockIdx.y;
    const int qt = gridDim.x - 1 - blockIdx.x;   // longest blocks launch first
    const int q0 = qt * BQ;
    const float slope = exp2f(-0.5f * (float)(h + 1));

    __shared__ float QsT[HDIM][BQ + 1];   // [d][row]
    __shared__ float KsT[HDIM][BT + 1];   // [d][t]
    __shared__ float Vs [BT][HDIM];       // [t][d]
    __shared__ float PsT[BT][BQ + 1];     // [t][row]

    const int tid = threadIdx.x;
    const int tr  = (tid >> 4) * 4;   // 4 query rows
    const int cg  = tid & 15;         // column group: cols cg + 16*j

    // load Q tile (transposed into smem)
    for (int f = tid; f < BQ * 16; f += 256) {
        int r = f >> 4, d4 = (f & 15) * 4;
        float4 v4 = *(const float4*)&Q[(size_t)(q0 + r) * DMODEL + h * HDIM + d4];
        QsT[d4 + 0][r] = v4.x; QsT[d4 + 1][r] = v4.y;
        QsT[d4 + 2][r] = v4.z; QsT[d4 + 3][r] = v4.w;
    }

    float m[4], l[4], o[4][4];
#pragma unroll
    for (int i = 0; i < 4; i++) {
        m[i] = -INFINITY; l[i] = 0.f;
#pragma unroll
        for (int j = 0; j < 4; j++) o[i][j] = 0.f;
    }

    const int ntiles = 2 * (qt + 1);    // BQ/BT = 2
    for (int t = 0; t < ntiles; t++) {
        const int t0 = t * BT;
        __syncthreads();   // protect smem reuse (and first-iter Q writes)

        // load K,V tile
        for (int f = tid; f < BT * 16; f += 256) {
            int r = f >> 4, d4 = (f & 15) * 4;
            float4 kv = *(const float4*)&K[(size_t)(t0 + r) * DMODEL + h * HDIM + d4];
            KsT[d4 + 0][r] = kv.x; KsT[d4 + 1][r] = kv.y;
            KsT[d4 + 2][r] = kv.z; KsT[d4 + 3][r] = kv.w;
            float4 vv = *(const float4*)&V[(size_t)(t0 + r) * DMODEL + h * HDIM + d4];
            *(float4*)&Vs[r][d4] = vv;
        }
        __syncthreads();

        // S = Q @ K^T  (4x2 per thread)
        float s[4][2];
#pragma unroll
        for (int i = 0; i < 4; i++) { s[i][0] = 0.f; s[i][1] = 0.f; }
#pragma unroll 8
        for (int d = 0; d < HDIM; d++) {
            float a0 = QsT[d][tr + 0], a1 = QsT[d][tr + 1];
            float a2 = QsT[d][tr + 2], a3 = QsT[d][tr + 3];
            float b0 = KsT[d][cg], b1 = KsT[d][cg + 16];
            s[0][0] += a0 * b0; s[0][1] += a0 * b1;
            s[1][0] += a1 * b0; s[1][1] += a1 * b1;
            s[2][0] += a2 * b0; s[2][1] += a2 * b1;
            s[3][0] += a3 * b0; s[3][1] += a3 * b1;
        }

        // scale + ALiBi + causal mask
#pragma unroll
        for (int i = 0; i < 4; i++) {
            int row = q0 + tr + i;
#pragma unroll
            for (int j = 0; j < 2; j++) {
                int col = t0 + cg + 16 * j;
                float val = s[i][j] * 0.125f - slope * (float)col;
                s[i][j] = (col <= row) ? val : -INFINITY;
            }
        }

        // online softmax (row reductions across 16-lane groups)
#pragma unroll
        for (int i = 0; i < 4; i++) {
            float v = fmaxf(s[i][0], s[i][1]);
            v = fmaxf(v, __shfl_xor_sync(0xffffffffu, v, 1));
            v = fmaxf(v, __shfl_xor_sync(0xffffffffu, v, 2));
            v = fmaxf(v, __shfl_xor_sync(0xffffffffu, v, 4));
            v = fmaxf(v, __shfl_xor_sync(0xffffffffu, v, 8));
            float mn = fmaxf(m[i], v);
            float sc = __expf(m[i] - mn);
            m[i] = mn;
            l[i] *= sc;
#pragma unroll
            for (int j = 0; j < 4; j++) o[i][j] *= sc;
            float p0 = __expf(s[i][0] - mn);
            float p1 = __expf(s[i][1] - mn);
            s[i][0] = p0; s[i][1] = p1;
            float rs = p0 + p1;
            rs += __shfl_xor_sync(0xffffffffu, rs, 1);
            rs += __shfl_xor_sync(0xffffffffu, rs, 2);
            rs += __shfl_xor_sync(0xffffffffu, rs, 4);
            rs += __shfl_xor_sync(0xffffffffu, rs, 8);
            l[i] += rs;
        }

        // stash P transposed for the PV gemm
#pragma unroll
        for (int i = 0; i < 4; i++) {
            PsT[cg     ][tr + i] = s[i][0];
            PsT[cg + 16][tr + i] = s[i][1];
        }
        __syncthreads();

        // O += P @ V  (4x4 per thread over d = cg + 16*j)
#pragma unroll 4
        for (int tt = 0; tt < BT; tt++) {
            float p0 = PsT[tt][tr + 0], p1 = PsT[tt][tr + 1];
            float p2 = PsT[tt][tr + 2], p3 = PsT[tt][tr + 3];
            float v0 = Vs[tt][cg], v1 = Vs[tt][cg + 16];
            float v2 = Vs[tt][cg + 32], v3 = Vs[tt][cg + 48];
            o[0][0] += p0 * v0; o[0][1] += p0 * v1; o[0][2] += p0 * v2; o[0][3] += p0 * v3;
            o[1][0] += p1 * v0; o[1][1] += p1 * v1; o[1][2] += p1 * v2; o[1][3] += p1 * v3;
            o[2][0] += p2 * v0; o[2][1] += p2 * v1; o[2][2] += p2 * v2; o[2][3] += p2 * v3;
            o[3][0] += p3 * v0; o[3][1] += p3 * v1; o[3][2] += p3 * v2; o[3][3] += p3 * v3;
        }
    }

    // epilogue: normalize and store to [S][D] layout
#pragma unroll
    for (int i = 0; i < 4; i++) {
        float inv = 1.f / l[i];
#pragma unroll
        for (int j = 0; j < 4; j++)
            O[(size_t)(q0 + tr + i) * DMODEL + h * HDIM + cg + 16 * j] = o[i][j] * inv;
    }
}

// ---------------------------------------------------------------------------
extern "C" void kernel_launch(void* const* d_in, const int* in_sizes, int n_in,
                              void* d_out, int out_size)
{
    const float* x  = (const float*)d_in[0];
    const float* Wq = (const float*)d_in[1];
    const float* bq = (const float*)d_in[2];
    const float* Wk = (const float*)d_in[3];
    const float* Wv = (const float*)d_in[4];
    const float* bv = (const float*)d_in[5];
    const float* Wo = (const float*)d_in[6];
    float* out = (float*)d_out;

    float *qp, *kp, *vp, *ap;
    cudaGetSymbolAddress((void**)&qp, g_q);
    cudaGetSymbolAddress((void**)&kp, g_k);
    cudaGetSymbolAddress((void**)&vp, g_v);
    cudaGetSymbolAddress((void**)&ap, g_attn);

    dim3 ggrid(DMODEL / 128, SLEN / 128);   // (8, 32)
    sgemm_nt<<<ggrid, 256>>>(x, Wq, bq, qp, SLEN, DMODEL, DMODEL);
    sgemm_nt<<<ggrid, 256>>>(x, Wk, nullptr, kp, SLEN, DMODEL, DMODEL);
    sgemm_nt<<<ggrid, 256>>>(x, Wv, bv, vp, SLEN, DMODEL, DMODEL);

    dim3 agrid(SLEN / BQ, NHEAD);           // (64, 16)
    flash_attn<<<agrid, 256>>>(qp, kp, vp, ap);

    sgemm_nt<<<ggrid, 256>>>(ap, Wo, nullptr, out, SLEN, DMODEL, DMODEL);
}